// round 4
// baseline (speedup 1.0000x reference)
#include <cuda_runtime.h>
#include <cuda_bf16.h>
#include <cstdint>

#define D 128
#define NMAX 50000
#define EMAX 800000
#define D4 (D/4)   // 32 float4 (= 32 ulonglong2) per row

typedef unsigned long long u64;

// ---------------- scratch (no allocations allowed) ----------------
__device__ int   g_deg[NMAX];          // 1 + in-degree (self-loop included)
__device__ float g_dinv[NMAX];
__device__ int   g_rowstart[NMAX];     // CSR row offsets (real edges only)
__device__ int   g_cur[NMAX];          // fill cursors
__device__ int   g_esrc[EMAX];         // CSR: src node per slot
__device__ float g_enorm[EMAX];        // CSR: dinv[src]*dinv[dst] per slot
__device__ float g_h[(size_t)NMAX * D];   // linear-transform output
__device__ float g_a[(size_t)NMAX * D];   // layer-1 activation
__device__ int   g_is64;               // 1 if edge_index is int64, 0 if int32

__device__ __forceinline__ int load_idx(const int* __restrict__ ei, size_t pos) {
    return g_is64 ? ei[2 * pos] : ei[pos];
}

// ---------------- f32x2 packed helpers ----------------
__device__ __forceinline__ u64 pack2(float s) {
    u64 r; asm("mov.b64 %0, {%1, %1};" : "=l"(r) : "f"(s)); return r;
}
__device__ __forceinline__ void fma2(u64& d, u64 a, u64 b) {
    asm("fma.rn.f32x2 %0, %1, %2, %0;" : "+l"(d) : "l"(a), "l"(b));
}

// ---------------- init degrees + dtype detect (fused) ----------------
__global__ void k_init(const int* __restrict__ ei, int n) {
    int i = blockIdx.x * blockDim.x + threadIdx.x;
    if (i < n) g_deg[i] = 1;              // self-loop contributes 1
    if (blockIdx.x == 0 && threadIdx.x == 0) {
        // int64 edge_index (values < 2^31) => every odd 32-bit word is 0
        int all0 = 1;
        for (int j = 0; j < 64; ++j)
            if (ei[2 * j + 1] != 0) { all0 = 0; break; }
        g_is64 = all0;
    }
}

__global__ void k_count(const int* __restrict__ ei, int E) {
    int e = blockIdx.x * blockDim.x + threadIdx.x;
    if (e < E) atomicAdd(&g_deg[load_idx(ei, (size_t)E + e)], 1);
}

// ---------------- scan of (deg-1) -> rowstart; cursors; dinv (fused) ------
__global__ void k_scan(int n) {
    __shared__ int part[1024];
    const int tid = threadIdx.x;
    const int chunk = (n + 1023) / 1024;
    const int beg = tid * chunk;
    const int end = min(beg + chunk, n);

    int s = 0;
    for (int i = beg; i < end; ++i) s += g_deg[i] - 1;
    part[tid] = s;
    __syncthreads();

    for (int off = 1; off < 1024; off <<= 1) {
        int v = (tid >= off) ? part[tid - off] : 0;
        __syncthreads();
        part[tid] += v;
        __syncthreads();
    }

    int run = (tid > 0) ? part[tid - 1] : 0;
    for (int i = beg; i < end; ++i) {
        int dg = g_deg[i];
        g_rowstart[i] = run;
        g_cur[i] = 0;
        g_dinv[i] = rsqrtf((float)dg);
        run += dg - 1;
    }
}

// ---------------- CSR fill ----------------
__global__ void k_fill(const int* __restrict__ ei, int E) {
    int e = blockIdx.x * blockDim.x + threadIdx.x;
    if (e >= E) return;
    int s = load_idx(ei, (size_t)e);
    int d = load_idx(ei, (size_t)E + e);
    int pos = g_rowstart[d] + atomicAdd(&g_cur[d], 1);
    g_esrc[pos]  = s;
    g_enorm[pos] = g_dinv[s] * g_dinv[d];
}

// ---------------- GEMM: C[M,128] = A[M,128] @ W[128,128] (FFMA2) ----------
// Block = 256 threads = 32 rows x (32 lanes * 4 cols).
// acc per row = 2 x f32x2. a-scalars packed (s,s) once, reused for both halves.
#define ROWFMA(acc, av, b0, b1, b2, b3) {              \
    u64 p;                                              \
    p = pack2(av.x); fma2(acc.x, p, b0.x); fma2(acc.y, p, b0.y); \
    p = pack2(av.y); fma2(acc.x, p, b1.x); fma2(acc.y, p, b1.y); \
    p = pack2(av.z); fma2(acc.x, p, b2.x); fma2(acc.y, p, b2.y); \
    p = pack2(av.w); fma2(acc.x, p, b3.x); fma2(acc.y, p, b3.y); }

__global__ void k_gemm(const float* __restrict__ A, const float* __restrict__ Wm,
                       float* __restrict__ C, int M) {
    int lane = threadIdx.x & 31;
    int rs   = threadIdx.x >> 5;
    int row0 = blockIdx.x * 32 + rs * 4;
    if (row0 >= M) return;

    const float4*     A4 = (const float4*)A;
    const ulonglong2* W2 = (const ulonglong2*)Wm;   // [k][lane], 16B each

    ulonglong2 acc0 = {0ull, 0ull}, acc1 = acc0, acc2 = acc0, acc3 = acc0;

    size_t ar0 = (size_t)(row0 + 0) * D4;
    size_t ar1 = (size_t)(row0 + 1) * D4;
    size_t ar2 = (size_t)(row0 + 2) * D4;
    size_t ar3 = (size_t)(row0 + 3) * D4;

#pragma unroll 2
    for (int k4 = 0; k4 < D4; ++k4) {
        float4 a0 = A4[ar0 + k4];
        float4 a1 = A4[ar1 + k4];
        float4 a2 = A4[ar2 + k4];
        float4 a3 = A4[ar3 + k4];
        int k = k4 * 4;
        ulonglong2 b0 = W2[(size_t)(k + 0) * D4 + lane];
        ulonglong2 b1 = W2[(size_t)(k + 1) * D4 + lane];
        ulonglong2 b2 = W2[(size_t)(k + 2) * D4 + lane];
        ulonglong2 b3 = W2[(size_t)(k + 3) * D4 + lane];

        ROWFMA(acc0, a0, b0, b1, b2, b3);
        ROWFMA(acc1, a1, b0, b1, b2, b3);
        ROWFMA(acc2, a2, b0, b1, b2, b3);
        ROWFMA(acc3, a3, b0, b1, b2, b3);
    }

    ulonglong2* C2 = (ulonglong2*)C;
    C2[ar0 + lane] = acc0;
    C2[ar1 + lane] = acc1;
    C2[ar2 + lane] = acc2;
    C2[ar3 + lane] = acc3;
}

// ---------------- CSR aggregation + self-loop + bias + ReLU --------------
// One warp per dst node, lane owns one float4 (4 cols). Unroll 4 for MLP.
#define FMA4(acc, s, b) { acc.x = fmaf(s, b.x, acc.x); acc.y = fmaf(s, b.y, acc.y); \
                          acc.z = fmaf(s, b.z, acc.z); acc.w = fmaf(s, b.w, acc.w); }

__global__ void k_agg_csr(const float* __restrict__ H,
                          const float* __restrict__ b,
                          float* __restrict__ out, int n) {
    int warp = (int)((blockIdx.x * (size_t)blockDim.x + threadIdx.x) >> 5);
    int lane = threadIdx.x & 31;
    if (warp >= n) return;
    int node = warp;

    const float4* H4 = (const float4*)H;

    float di = g_dinv[node];
    float sl = di * di;

    float4 acc = H4[(size_t)node * D4 + lane];   // self-loop
    acc.x *= sl; acc.y *= sl; acc.z *= sl; acc.w *= sl;

    int p   = g_rowstart[node];
    int end = p + (g_deg[node] - 1);

    for (; p + 3 < end; p += 4) {
        int   s0 = g_esrc[p],   s1 = g_esrc[p+1], s2 = g_esrc[p+2], s3 = g_esrc[p+3];
        float n0 = g_enorm[p],  n1 = g_enorm[p+1], n2 = g_enorm[p+2], n3 = g_enorm[p+3];
        float4 v0 = H4[(size_t)s0 * D4 + lane];
        float4 v1 = H4[(size_t)s1 * D4 + lane];
        float4 v2 = H4[(size_t)s2 * D4 + lane];
        float4 v3 = H4[(size_t)s3 * D4 + lane];
        FMA4(acc, n0, v0);
        FMA4(acc, n1, v1);
        FMA4(acc, n2, v2);
        FMA4(acc, n3, v3);
    }
    for (; p < end; ++p) {
        int   s0 = g_esrc[p];
        float n0 = g_enorm[p];
        float4 v0 = H4[(size_t)s0 * D4 + lane];
        FMA4(acc, n0, v0);
    }

    float4 bv = ((const float4*)b)[lane];
    float4 r;
    r.x = fmaxf(acc.x + bv.x, 0.f);
    r.y = fmaxf(acc.y + bv.y, 0.f);
    r.z = fmaxf(acc.z + bv.z, 0.f);
    r.w = fmaxf(acc.w + bv.w, 0.f);
    ((float4*)out)[(size_t)node * D4 + lane] = r;
}

// ---------------- launch ----------------
extern "C" void kernel_launch(void* const* d_in, const int* in_sizes, int n_in,
                              void* d_out, int out_size) {
    const float* x  = (const float*)d_in[0];
    const int*   ei = (const int*)d_in[1];
    const float* W1 = (const float*)d_in[2];
    const float* b1 = (const float*)d_in[3];
    const float* W2 = (const float*)d_in[4];
    const float* b2 = (const float*)d_in[5];
    float* out = (float*)d_out;

    int n = in_sizes[0] / D;        // 50000
    int E = in_sizes[1] / 2;        // 800000

    float *h, *a;
    cudaGetSymbolAddress((void**)&h, g_h);
    cudaGetSymbolAddress((void**)&a, g_a);

    // ---- setup: degrees+detect, count, scan(+dinv), CSR fill ----
    k_init<<<(n + 255) / 256, 256>>>(ei, n);
    k_count<<<(E + 255) / 256, 256>>>(ei, E);
    k_scan<<<1, 1024>>>(n);
    k_fill<<<(E + 255) / 256, 256>>>(ei, E);

    int aggBlocks = (n * 32 + 255) / 256;   // 1 warp per node

    // ---- layer 1 ----
    k_gemm<<<(n + 31) / 32, 256>>>(x, W1, h, n);
    k_agg_csr<<<aggBlocks, 256>>>(h, b1, a, n);

    // ---- layer 2 ----
    k_gemm<<<(n + 31) / 32, 256>>>(a, W2, h, n);
    k_agg_csr<<<aggBlocks, 256>>>(h, b2, out, n);
}